// round 15
// baseline (speedup 1.0000x reference)
#include <cuda_runtime.h>

#define Bn   2
#define Tn   7
#define Hn   128
#define Wn   128
#define Pn   343            // 7*7*7 taps
#define Un   16
#define HW   (Hn*Wn)        // 16384
#define WT   32             // w-tile per block
#define HT   2              // h rows per block
#define GH   8              // patch gh rows: 7 + HT - 1
#define RL   40             // padded patch row length (WT+6=38 -> 40)
#define TSTR (GH*RL)        // per-t stride (floats)
#define CSTR (Tn*TSTR)      // per-channel stride (floats)
#define NT   256

// R15: WT=32 -> warp streams are FULL 128B lines (R14's WT=16 gave 64B
// half-line requests, L1 63.5% and climbing); HT=2 keeps smem at 26.9KB.
// Grid 512, 4 blocks x 8 warps resident = 32 warps/SM, single wave.
// 64-reg ceiling (64K/1024thr) -> reg-lean loop: stage 4 taps, exp IN PLACE,
// per-channel patch windows in 8 reused regs; phase B reuses staging regs.
// Fused softmax-without-max: filt (719MB) streamed exactly once via __ldcs.
__global__ __launch_bounds__(NT, 4)
void dynfilt_kernel(const float* __restrict__ x,
                    const float* __restrict__ filt,
                    float* __restrict__ out)
{
    __shared__ float sm[3 * CSTR];   // 26.9 KB

    const int bx    = blockIdx.x;
    const int wq    = bx & 3;            // w quarter (4 tiles of 32)
    const int hp    = (bx >> 2) & 63;    // h pair index
    const int b     = bx >> 8;           // batch
    const int tid   = threadIdx.x;
    const int wg    = tid & 7;           // 0..7 -> w0 = 4*wg
    const int hh    = (tid >> 3) & 1;    // 0..1
    const int u     = tid >> 4;          // 0..15
    const int wbase = wq * WT;
    const int h0    = hp * HT;
    const int h     = h0 + hh;

    // ---- stage x patches (fp32): sm[((c*7+t)*GH+g)*RL + j]
    //      g = gh-(h0-3) in [0,8), j = gw-(wbase-3) in [0,38), zero pad ----
    for (int idx = tid; idx < 3 * CSTR; idx += NT) {
        int j = idx % RL;
        int g = (idx / RL) % GH;
        int t = (idx / TSTR) % Tn;
        int c = idx / CSTR;
        int gh = h0 - 3 + g;
        int gw = wbase - 3 + j;
        float v = 0.f;
        if (j < WT + 6 && (unsigned)gh < (unsigned)Hn && (unsigned)gw < (unsigned)Wn)
            v = x[(((size_t)(b * 3 + c) * Tn + t) * Hn + gh) * Wn + gw];
        sm[idx] = v;
    }
    __syncthreads();

    float acc0[4] = {0.f, 0.f, 0.f, 0.f};
    float acc1[4] = {0.f, 0.f, 0.f, 0.f};
    float acc2[4] = {0.f, 0.f, 0.f, 0.f};
    float lsum[4] = {0.f, 0.f, 0.f, 0.f};

    // filt[b, p, u, h, w]; per-tap stride = Un*HW elems (1 MB).
    const size_t TAP = (size_t)Un * HW;
    const float* fp = filt + (((size_t)b * Pn) * Un + (size_t)u) * HW
                           + (size_t)h * Wn + wbase + 4 * wg;

    #pragma unroll 1
    for (int r = 0; r < 49; ++r) {
        const int t  = r / 7;
        const int kh = r % 7;
        const float* srow = sm + t * TSTR + (hh + kh) * RL + 4 * wg;  // 16B aligned

        // ================= phase A: taps 0..3 =================
        float4 f0 = __ldcs((const float4*)(fp + 0 * TAP));
        float4 f1 = __ldcs((const float4*)(fp + 1 * TAP));
        float4 f2 = __ldcs((const float4*)(fp + 2 * TAP));
        float4 f3 = __ldcs((const float4*)(fp + 3 * TAP));

        // exp in place
        f0.x = __expf(f0.x); f0.y = __expf(f0.y); f0.z = __expf(f0.z); f0.w = __expf(f0.w);
        f1.x = __expf(f1.x); f1.y = __expf(f1.y); f1.z = __expf(f1.z); f1.w = __expf(f1.w);
        f2.x = __expf(f2.x); f2.y = __expf(f2.y); f2.z = __expf(f2.z); f2.w = __expf(f2.w);
        f3.x = __expf(f3.x); f3.y = __expf(f3.y); f3.z = __expf(f3.z); f3.w = __expf(f3.w);
        lsum[0] += f0.x + f1.x + f2.x + f3.x;
        lsum[1] += f0.y + f1.y + f2.y + f3.y;
        lsum[2] += f0.z + f1.z + f2.z + f3.z;
        lsum[3] += f0.w + f1.w + f2.w + f3.w;

        // per-channel: patch window p[0..7], taps 0..3
        {
            float4 q0, q1;
            #define PHASE_A(C, ACC)                                           \
                q0 = *(const float4*)(srow + (C) * CSTR);                     \
                q1 = *(const float4*)(srow + (C) * CSTR + 4);                 \
                ACC[0] += f0.x * q0.x + f1.x * q0.y + f2.x * q0.z + f3.x * q0.w; \
                ACC[1] += f0.y * q0.y + f1.y * q0.z + f2.y * q0.w + f3.y * q1.x; \
                ACC[2] += f0.z * q0.z + f1.z * q0.w + f2.z * q1.x + f3.z * q1.y; \
                ACC[3] += f0.w * q0.w + f1.w * q1.x + f2.w * q1.y + f3.w * q1.z;
            PHASE_A(0, acc0)
            PHASE_A(1, acc1)
            PHASE_A(2, acc2)
            #undef PHASE_A
        }

        // ================= phase B: taps 4..6 =================
        f0 = __ldcs((const float4*)(fp + 4 * TAP));
        f1 = __ldcs((const float4*)(fp + 5 * TAP));
        f2 = __ldcs((const float4*)(fp + 6 * TAP));

        f0.x = __expf(f0.x); f0.y = __expf(f0.y); f0.z = __expf(f0.z); f0.w = __expf(f0.w);
        f1.x = __expf(f1.x); f1.y = __expf(f1.y); f1.z = __expf(f1.z); f1.w = __expf(f1.w);
        f2.x = __expf(f2.x); f2.y = __expf(f2.y); f2.z = __expf(f2.z); f2.w = __expf(f2.w);
        lsum[0] += f0.x + f1.x + f2.x;
        lsum[1] += f0.y + f1.y + f2.y;
        lsum[2] += f0.z + f1.z + f2.z;
        lsum[3] += f0.w + f1.w + f2.w;

        // per-channel: patch window p[4..11], taps 4..6
        {
            float4 q1, q2;
            #define PHASE_B(C, ACC)                                           \
                q1 = *(const float4*)(srow + (C) * CSTR + 4);                 \
                q2 = *(const float4*)(srow + (C) * CSTR + 8);                 \
                ACC[0] += f0.x * q1.x + f1.x * q1.y + f2.x * q1.z;            \
                ACC[1] += f0.y * q1.y + f1.y * q1.z + f2.y * q1.w;            \
                ACC[2] += f0.z * q1.z + f1.z * q1.w + f2.z * q2.x;            \
                ACC[3] += f0.w * q1.w + f1.w * q2.x + f2.w * q2.y;
            PHASE_B(0, acc0)
            PHASE_B(1, acc1)
            PHASE_B(2, acc2)
            #undef PHASE_B
        }

        fp += 7 * TAP;
    }

    // ---- epilogue: normalize + pixel shuffle ----
    // u -> (ur = u/4, uc = u%4); thread w's are wbase+4wg+i -> col 4w+uc.
    const int ur = u >> 2, uc = u & 3;
    const int Ho = Hn * 4, Wo = Wn * 4;
    const size_t cstride = (size_t)Ho * Wo;
    size_t obase = ((size_t)(b * 3) * Ho + (4 * h + ur)) * Wo
                 + (size_t)4 * (wbase + 4 * wg) + uc;

    #pragma unroll
    for (int i = 0; i < 4; ++i) {
        float inv = 1.f / lsum[i];
        out[obase + 4 * i]                = acc0[i] * inv;
        out[obase + 4 * i + cstride]      = acc1[i] * inv;
        out[obase + 4 * i + 2 * cstride]  = acc2[i] * inv;
    }
}

extern "C" void kernel_launch(void* const* d_in, const int* in_sizes, int n_in,
                              void* d_out, int out_size)
{
    const float* x    = (const float*)d_in[0];   // [2,3,7,128,128]
    const float* filt = (const float*)d_in[1];   // [2,343,16,128,128]
    float* out        = (float*)d_out;           // [2,3,512,512]

    // grid = B * (H/HT) * (W/WT) = 2*64*4 = 512 blocks, 256 threads.
    // 148 SMs x 4 resident (26.9KB smem, 64 regs) = 592 >= 512: single wave,
    // 32 warps/SM. No carveout attribute (R12 lesson).
    dynfilt_kernel<<<Bn * (Hn / HT) * (Wn / WT), NT>>>(x, filt, out);
}